// round 4
// baseline (speedup 1.0000x reference)
#include <cuda_runtime.h>
#include <cuda_bf16.h>
#include <cstdint>

#define B_   64
#define NR_  16384
#define IC_  16
#define NC_  10
#define OC_  16
#define CO_  160
#define SPLITK 16
#define KCH  (NR_/SPLITK)   // 1024
#define KB   32
#define NCH  (KCH/KB)       // 32

// -------- device scratch (no allocations allowed) --------
__device__ __nv_bfloat16 g_xhi[(size_t)IC_*B_*NR_];     // x hi  [i][b][r]
__device__ __nv_bfloat16 g_xlo[(size_t)IC_*B_*NR_];     // x lo  [i][b][r]
__device__ float g_part[(size_t)SPLITK*B_*IC_*CO_];     // split-K partials [s][b][i][co]
__device__ float g_v   [B_*CO_];                        // v_j [b][co]

// GEMM smem layout (bytes):
//  ws hi: 160 rows x 36 halves = 11520   (pad 36 -> conflict-free B-frag LDS)
//  ws lo: 11520
//  xs hi: 3 stages x (64 rows x 40 halves) = 15360 (pad 40 -> conflict-free A-frag)
//  xs lo: 15360
#define OFF_WSL 11520
#define OFF_XSH 23040
#define OFF_XSL 38400
#define SMEM_G  53760
#define XST     5120

static __device__ __forceinline__ void mma16816(float* c, const uint32_t* a,
                                                const uint32_t* b) {
    asm volatile(
        "mma.sync.aligned.m16n8k16.row.col.f32.bf16.bf16.f32 "
        "{%0,%1,%2,%3}, {%4,%5,%6,%7}, {%8,%9}, {%0,%1,%2,%3};"
        : "+f"(c[0]), "+f"(c[1]), "+f"(c[2]), "+f"(c[3])
        : "r"(a[0]), "r"(a[1]), "r"(a[2]), "r"(a[3]), "r"(b[0]), "r"(b[1]));
}
static __device__ __forceinline__ uint32_t smem_u32(const void* p) {
    uint32_t a;
    asm("{ .reg .u64 t; cvta.to.shared.u64 t, %1; cvt.u32.u64 %0, t; }"
        : "=r"(a) : "l"(p));
    return a;
}
static __device__ __forceinline__ void cp8(uint32_t dst, const void* src) {
    asm volatile("cp.async.ca.shared.global [%0], [%1], 8;"
                 :: "r"(dst), "l"(src));
}
static __device__ __forceinline__ void cp_commit() {
    asm volatile("cp.async.commit_group;" ::: "memory");
}
template <int N> static __device__ __forceinline__ void cp_wait() {
    asm volatile("cp.async.wait_group %0;" :: "n"(N) : "memory");
}
// pack 2 fp32 -> bf16x2 (RN), also return residuals packed
static __device__ __forceinline__ void pack_split(float f0, float f1,
                                                  uint32_t& h, uint32_t& l) {
    asm("cvt.rn.bf16x2.f32 %0, %1, %2;" : "=r"(h) : "f"(f1), "f"(f0));
    float h0 = __uint_as_float(h << 16);
    float h1 = __uint_as_float(h & 0xFFFF0000u);
    float l0 = f0 - h0, l1 = f1 - h1;
    asm("cvt.rn.bf16x2.f32 %0, %1, %2;" : "=r"(l) : "f"(l1), "f"(l0));
}
static __device__ __forceinline__ void bsplit(float v, __nv_bfloat16& h,
                                              __nv_bfloat16& l) {
    h = __float2bfloat16(v);
    l = __float2bfloat16(v - __bfloat162float(h));
}

// ---------------------------------------------------------------------------
// 1) Transpose + bf16 split: x[b][r][i] -> xhi/xlo [i][b][r]
// ---------------------------------------------------------------------------
__global__ void k_transpose(const float* __restrict__ x) {
    __shared__ float tile[16][64];
    const int b = blockIdx.y, tid = threadIdx.x;
    const int r = tid >> 2, i4 = (tid & 3) * 4;
    const int i = tid >> 4, rs = (tid & 15) * 4;
    for (int tt = 0; tt < 4; tt++) {
        const int r0 = (blockIdx.x * 4 + tt) * 64;
        float4 v = *(const float4*)(x + ((size_t)b * NR_ + r0 + r) * IC_ + i4);
        tile[i4 + 0][r] = v.x; tile[i4 + 1][r] = v.y;
        tile[i4 + 2][r] = v.z; tile[i4 + 3][r] = v.w;
        __syncthreads();
        float4 o = *(const float4*)&tile[i][rs];
        union { __nv_bfloat16 h[4]; uint2 u; } ph, pl;
        bsplit(o.x, ph.h[0], pl.h[0]);
        bsplit(o.y, ph.h[1], pl.h[1]);
        bsplit(o.z, ph.h[2], pl.h[2]);
        bsplit(o.w, ph.h[3], pl.h[3]);
        const size_t dst = ((size_t)i * B_ + b) * NR_ + r0 + rs;
        *(uint2*)(g_xhi + dst) = ph.u;
        *(uint2*)(g_xlo + dst) = pl.u;
        __syncthreads();
    }
}

// ---------------------------------------------------------------------------
// 2) bf16x3 HMMA GEMM, cp.async pipelined. grid (SPLITK, IC), 256 threads.
//    A = x (m=64), B = W (n=160). 8 warps: wm{0,1} x 32 b-rows, wn{0..3} x 40 co.
// ---------------------------------------------------------------------------
__global__ __launch_bounds__(256, 2) void k_gemm(const float* __restrict__ Wg) {
    extern __shared__ char smem[];
    __nv_bfloat16* wsh = (__nv_bfloat16*)(smem);
    __nv_bfloat16* wsl = (__nv_bfloat16*)(smem + OFF_WSL);
    const uint32_t sbase = smem_u32(smem);

    const int i = blockIdx.y, split = blockIdx.x, t = threadIdx.x;
    const int warp = t >> 5, lane = t & 31;
    const int wm = warp >> 2, wn = warp & 3;
    const int r0 = split * KCH;
    const float* Wi = Wg + (size_t)i * CO_ * NR_;
    const __nv_bfloat16* Xh = g_xhi + (size_t)i * B_ * NR_;
    const __nv_bfloat16* Xl = g_xlo + (size_t)i * B_ * NR_;

    float acc[2][5][4];
#pragma unroll
    for (int m = 0; m < 2; m++)
#pragma unroll
        for (int n = 0; n < 5; n++)
#pragma unroll
            for (int q = 0; q < 4; q++) acc[m][n][q] = 0.f;

    const int wrow = t >> 3, wk4 = t & 7;     // W LDG: 5 rows strided 32
    float4 wr[5];

#define LDGW(nn) { \
        const float* wp = Wi + (size_t)wrow * NR_ + r0 + (nn) * KB + wk4 * 4; \
        _Pragma("unroll") \
        for (int q = 0; q < 5; q++) wr[q] = *(const float4*)(wp + (size_t)q * 32 * NR_); }

    // x cp.async: 4 x 8B per thread per chunk (hi: q<2, lo: q>=2)
#define XCP(nn, ss) { \
        _Pragma("unroll") \
        for (int q = 0; q < 4; q++) { \
            const int i2 = t + (q & 1) * 256; \
            const int row = i2 >> 3, k4 = i2 & 7; \
            const __nv_bfloat16* src = ((q < 2) ? Xh : Xl) \
                + (size_t)row * NR_ + r0 + (nn) * KB + k4 * 4; \
            uint32_t dst = sbase + ((q < 2) ? OFF_XSH : OFF_XSL) \
                + (ss) * XST + row * 80 + k4 * 8; \
            cp8(dst, src); \
        } cp_commit(); }

    XCP(0, 0);
    XCP(1, 1);
    LDGW(0);

    for (int n = 0; n < NCH; n++) {
        __syncthreads();                       // close compute(n-1): ws + xs reuse safe
        // convert W chunk n (registers) -> ws (single buffer)
#pragma unroll
        for (int q = 0; q < 5; q++) {
            const int co = wrow + q * 32;
            uint2 h, l;
            pack_split(wr[q].x, wr[q].y, h.x, l.x);
            pack_split(wr[q].z, wr[q].w, h.y, l.y);
            const int so = co * 36 + wk4 * 4;
            *(uint2*)(wsh + so) = h;
            *(uint2*)(wsl + so) = l;
        }
        if (n + 1 < NCH) LDGW(n + 1);
        if (n + 2 < NCH) XCP(n + 2, (n + 2) % 3);
        if (n + 2 < NCH)      cp_wait<2>();
        else if (n + 1 < NCH) cp_wait<1>();
        else                  cp_wait<0>();
        __syncthreads();                       // ws + xs(n) ready

        const __nv_bfloat16* xh = (const __nv_bfloat16*)(smem + OFF_XSH + (n % 3) * XST);
        const __nv_bfloat16* xl = (const __nv_bfloat16*)(smem + OFF_XSL + (n % 3) * XST);
#pragma unroll
        for (int kb = 0; kb < 2; kb++) {
            const int kc = kb * 16 + (lane & 3) * 2;
            uint32_t ah[2][4], al[2][4];
#pragma unroll
            for (int mt = 0; mt < 2; mt++) {
                const int rr = wm * 32 + mt * 16 + (lane >> 2);
                const __nv_bfloat16* p = xh + rr * 40 + kc;
                const __nv_bfloat16* q = xl + rr * 40 + kc;
                ah[mt][0] = *(const uint32_t*)p;
                ah[mt][1] = *(const uint32_t*)(p + 320);   // row+8
                ah[mt][2] = *(const uint32_t*)(p + 8);     // k+8
                ah[mt][3] = *(const uint32_t*)(p + 328);
                al[mt][0] = *(const uint32_t*)q;
                al[mt][1] = *(const uint32_t*)(q + 320);
                al[mt][2] = *(const uint32_t*)(q + 8);
                al[mt][3] = *(const uint32_t*)(q + 328);
            }
#pragma unroll
            for (int nf = 0; nf < 5; nf++) {
                const int cb = wn * 40 + nf * 8 + (lane >> 2);
                const __nv_bfloat16* p = wsh + cb * 36 + kc;
                const __nv_bfloat16* q = wsl + cb * 36 + kc;
                uint32_t bh[2], bl[2];
                bh[0] = *(const uint32_t*)p;
                bh[1] = *(const uint32_t*)(p + 8);
                bl[0] = *(const uint32_t*)q;
                bl[1] = *(const uint32_t*)(q + 8);
#pragma unroll
                for (int mt = 0; mt < 2; mt++) {
                    mma16816(acc[mt][nf], ah[mt], bh);
                    mma16816(acc[mt][nf], ah[mt], bl);
                    mma16816(acc[mt][nf], al[mt], bh);
                }
            }
        }
    }

    // epilogue: C rows = b, cols = co.  g_part[split][b][i][co]
    float* base = g_part + (size_t)split * (B_ * IC_ * CO_) + (size_t)i * CO_;
#pragma unroll
    for (int mt = 0; mt < 2; mt++) {
        const int b = wm * 32 + mt * 16 + (lane >> 2);
#pragma unroll
        for (int nf = 0; nf < 5; nf++) {
            const int co = wn * 40 + nf * 8 + (lane & 3) * 2;
            float* d0 = base + (size_t)b * (IC_ * CO_) + co;
            *(float2*)d0 = make_float2(acc[mt][nf][0], acc[mt][nf][1]);
            *(float2*)(d0 + 8 * IC_ * CO_) =
                make_float2(acc[mt][nf][2], acc[mt][nf][3]);   // b+8
        }
    }
}

// ---------------------------------------------------------------------------
// 3) Fused split-K reduce + full routing (3 iters): one CTA per capsule c.
// ---------------------------------------------------------------------------
#define ISTR 1032
__global__ __launch_bounds__(1024) void k_route_all(float* __restrict__ out) {
    extern __shared__ float sm[];
    float* u_s  = sm;                       // [16][ISTR]
    float* v_s  = sm + 16 * ISTR;           // [1024]
    float* csh  = v_s + 1024;               // [16]
    float* bijs = csh + 16;                 // [16]
    float* ared = bijs + 16;                // [32]
    const int c = blockIdx.x, t = threadIdx.x;

    // fused reduce: thread owns (b0+16j, i, o4), sums 16 splits
    {
        const int o4 = t & 3, i = (t >> 2) & 15, b0 = t >> 6;
#pragma unroll
        for (int j = 0; j < 4; j++) {
            const int b = b0 + 16 * j;
            const size_t off = ((size_t)b * IC_ + i) * CO_ + c * OC_ + o4 * 4;
            float4 s = make_float4(0.f, 0.f, 0.f, 0.f);
#pragma unroll
            for (int sp = 0; sp < SPLITK; sp++) {
                float4 p = *(const float4*)(g_part + (size_t)sp * (B_ * IC_ * CO_) + off);
                s.x += p.x; s.y += p.y; s.z += p.z; s.w += p.w;
            }
            *(float4*)(u_s + i * ISTR + b * 16 + o4 * 4) = s;
        }
    }
    if (t < 16) bijs[t] = 0.f;
    __syncthreads();

    for (int it = 0; it < 3; it++) {
        if (t < 32) {   // softmax over i within one warp (width-16)
            float bv = (t < 16) ? bijs[t] : -1e30f;
            float m = bv;
#pragma unroll
            for (int off = 8; off; off >>= 1)
                m = fmaxf(m, __shfl_xor_sync(0xffffffffu, m, off, 16));
            float e = expf(bv - m), sum = e;
#pragma unroll
            for (int off = 8; off; off >>= 1)
                sum += __shfl_xor_sync(0xffffffffu, sum, off, 16);
            if (t < 16) csh[t] = e / sum;
        }
        __syncthreads();
        {
            float s = 0.f;
#pragma unroll
            for (int i = 0; i < IC_; i++) s += csh[i] * u_s[i * ISTR + t];
            v_s[t] = s * fabsf(s) / (1.f + s * s);
        }
        __syncthreads();
        if (it < 2) {   // agreement: 32 warps, (i, half) each
            const int w = t >> 5, l = t & 31;
            const int i = w & 15, j0 = (w >> 4) * 512;
            float a = 0.f;
            for (int j = j0 + l; j < j0 + 512; j += 32)
                a += u_s[i * ISTR + j] * v_s[j];
#pragma unroll
            for (int off = 16; off; off >>= 1)
                a += __shfl_down_sync(0xffffffffu, a, off);
            if (l == 0) ared[(w >> 4) * 16 + i] = a;
            __syncthreads();
            if (t < 16) bijs[t] += (ared[t] + ared[16 + t]) * (1.0f / B_);
            __syncthreads();
        }
    }
    {
        const int b = t >> 4, o = t & 15;
        const float v = v_s[t];
        g_v[b * CO_ + c * OC_ + o] = v;
        out[B_ + b * CO_ + c * OC_ + o] = v;
    }
}

// ---------------------------------------------------------------------------
// 4) pred = sigmoid(v . fc_w + fc_b)
// ---------------------------------------------------------------------------
__global__ void k_final(const float* __restrict__ fcw,
                        const float* __restrict__ fcb,
                        float* __restrict__ out) {
    const int b = blockIdx.x, t = threadIdx.x;
    float p = g_v[b * CO_ + t] * fcw[t];
#pragma unroll
    for (int off = 16; off; off >>= 1) p += __shfl_down_sync(0xffffffffu, p, off);
    __shared__ float red[5];
    if ((t & 31) == 0) red[t >> 5] = p;
    __syncthreads();
    if (t == 0) {
        const float s = red[0] + red[1] + red[2] + red[3] + red[4] + fcb[0];
        out[b] = 1.f / (1.f + expf(-s));
    }
}

// ---------------------------------------------------------------------------
extern "C" void kernel_launch(void* const* d_in, const int* in_sizes, int n_in,
                              void* d_out, int out_size) {
    const float* x   = (const float*)d_in[0];
    const float* W   = (const float*)d_in[1];
    const float* fcw = (const float*)d_in[2];
    const float* fcb = (const float*)d_in[3];
    float* out = (float*)d_out;

    const int route_smem = (16 * ISTR + 1024 + 16 + 16 + 32) * 4;
    cudaFuncSetAttribute(k_gemm, cudaFuncAttributeMaxDynamicSharedMemorySize, SMEM_G);
    cudaFuncSetAttribute(k_route_all, cudaFuncAttributeMaxDynamicSharedMemorySize,
                         route_smem);

    k_transpose<<<dim3(NR_ / 256, B_), 256>>>(x);
    k_gemm<<<dim3(SPLITK, IC_), 256, SMEM_G>>>(W);
    k_route_all<<<NC_, 1024, route_smem>>>(out);
    k_final<<<B_, CO_>>>(fcw, fcb, out);
}

// round 9
// speedup vs baseline: 1.1432x; 1.1432x over previous
#include <cuda_runtime.h>
#include <cuda_fp16.h>
#include <cstdint>

#define B_   64
#define NR_  16384
#define IC_  16
#define NC_  10
#define OC_  16
#define CO_  160
#define SPLITK 16
#define KCH  (NR_/SPLITK)   // 1024
#define KB   32
#define NCH  (KCH/KB)       // 32

// -------- device scratch (no allocations allowed) --------
__device__ __half g_xhi[(size_t)IC_*B_*NR_];            // x hi fp16 [i][b][r]
__device__ __half g_xlo[(size_t)IC_*B_*NR_];            // x residual fp16
__device__ float g_part[(size_t)SPLITK*B_*IC_*CO_];     // split-K partials [s][b][i][co]
__device__ float g_fcp[NC_*B_];                         // fc partial dots [c][b]

// GEMM smem byte offsets (all rows padded to 40 halves = 80B: 16B-aligned,
// 5*row mod 8 distinct -> conflict-free ldmatrix)
#define WSH_OFF 0            // W hi: 2 stages x 160x40 halves (12800B/stage)
#define WSL_OFF 25600        // W lo
#define XSH_OFF 51200        // x hi: 3 stages x 64x40 halves (5120B/stage)
#define XSL_OFF 66560        // x lo
#define SMEM_G  81920

static __device__ __forceinline__ void mma16816(float* c, const uint32_t* a,
                                                const uint32_t* b) {
    asm volatile(
        "mma.sync.aligned.m16n8k16.row.col.f32.f16.f16.f32 "
        "{%0,%1,%2,%3}, {%4,%5,%6,%7}, {%8,%9}, {%0,%1,%2,%3};"
        : "+f"(c[0]), "+f"(c[1]), "+f"(c[2]), "+f"(c[3])
        : "r"(a[0]), "r"(a[1]), "r"(a[2]), "r"(a[3]), "r"(b[0]), "r"(b[1]));
}
static __device__ __forceinline__ void ldsm4(uint32_t* r, uint32_t addr) {
    asm volatile("ldmatrix.sync.aligned.m8n8.x4.shared.b16 {%0,%1,%2,%3}, [%4];"
                 : "=r"(r[0]), "=r"(r[1]), "=r"(r[2]), "=r"(r[3]) : "r"(addr));
}
static __device__ __forceinline__ void ldsm2(uint32_t* r, uint32_t addr) {
    asm volatile("ldmatrix.sync.aligned.m8n8.x2.shared.b16 {%0,%1}, [%2];"
                 : "=r"(r[0]), "=r"(r[1]) : "r"(addr));
}
static __device__ __forceinline__ uint32_t smem_u32(const void* p) {
    uint32_t a;
    asm("{ .reg .u64 t; cvta.to.shared.u64 t, %1; cvt.u32.u64 %0, t; }"
        : "=r"(a) : "l"(p));
    return a;
}
static __device__ __forceinline__ void cp16(uint32_t dst, const void* src) {
    asm volatile("cp.async.cg.shared.global [%0], [%1], 16;" :: "r"(dst), "l"(src));
}
static __device__ __forceinline__ void cp_commit() {
    asm volatile("cp.async.commit_group;" ::: "memory");
}
template <int N> static __device__ __forceinline__ void cp_wait() {
    asm volatile("cp.async.wait_group %0;" :: "n"(N) : "memory");
}
static __device__ __forceinline__ void hsplit(float v, __half& h, __half& l) {
    h = __float2half_rn(v);
    l = __float2half_rn(v - __half2float(h));
}

// ---------------------------------------------------------------------------
// 1) Transpose + fp16 hi/lo split: x[b][r][i] -> g_xhi/g_xlo [i][b][r]
// ---------------------------------------------------------------------------
__global__ void k_transpose(const float* __restrict__ x) {
    __shared__ float tile[16][64];
    const int b = blockIdx.y, tid = threadIdx.x;
    const int r = tid >> 2, i4 = (tid & 3) * 4;
    const int i = tid >> 4, rs = (tid & 15) * 4;
    for (int tt = 0; tt < 4; tt++) {
        const int r0 = (blockIdx.x * 4 + tt) * 64;
        float4 v = *(const float4*)(x + ((size_t)b * NR_ + r0 + r) * IC_ + i4);
        tile[i4 + 0][r] = v.x; tile[i4 + 1][r] = v.y;
        tile[i4 + 2][r] = v.z; tile[i4 + 3][r] = v.w;
        __syncthreads();
        float4 o = *(const float4*)&tile[i][rs];
        union { __half h[4]; uint2 u; } ph, pl;
        hsplit(o.x, ph.h[0], pl.h[0]);
        hsplit(o.y, ph.h[1], pl.h[1]);
        hsplit(o.z, ph.h[2], pl.h[2]);
        hsplit(o.w, ph.h[3], pl.h[3]);
        const size_t dst = ((size_t)i * B_ + b) * NR_ + r0 + rs;
        *(uint2*)(g_xhi + dst) = ph.u;
        *(uint2*)(g_xlo + dst) = pl.u;
        __syncthreads();
    }
}

// ---------------------------------------------------------------------------
// 2) fp16x3 HMMA GEMM, ldmatrix fragments, cp.async x. grid (SPLITK, IC),
//    256 threads (8 warps wm2 x wn4). A=x (m64), B=W (n160), KB=32.
// ---------------------------------------------------------------------------
__global__ __launch_bounds__(256, 2) void k_gemm(const float* __restrict__ Wg) {
    extern __shared__ char smem[];
    const uint32_t sbase = smem_u32(smem);

    const int i = blockIdx.y, split = blockIdx.x, t = threadIdx.x;
    const int warp = t >> 5, lane = t & 31;
    const int wm = warp >> 2, wn = warp & 3;
    const int r0 = split * KCH;
    const float* Wi = Wg + (size_t)i * CO_ * NR_;
    const __half* Xh = g_xhi + (size_t)i * B_ * NR_;
    const __half* Xl = g_xlo + (size_t)i * B_ * NR_;

    float acc[2][5][4];
#pragma unroll
    for (int m = 0; m < 2; m++)
#pragma unroll
        for (int n = 0; n < 5; n++)
#pragma unroll
            for (int q = 0; q < 4; q++) acc[m][n][q] = 0.f;

    // ldmatrix per-lane address components
    const int tA = lane >> 3;
    const int a_ml  = (tA & 1) * 8 + (lane & 7);   // m-local within 16
    const int a_ko  = (tA >> 1) * 8;               // k offset 0/8
    const int b_bn  = lane & 7;
    const int b_ko  = (tA & 1) * 8;
    const int b_p   = tA >> 1;                     // 0/1: which nf of the pair
    const int tC    = (lane >> 3) & 1;             // for x2

    // W LDG: 5 rows strided 32, one float4 each
    const int wrow = t >> 3, wk4 = t & 7;
    float4 wr[5];

#define LDGW(nn) { \
        const float* wp = Wi + (size_t)wrow * NR_ + r0 + (nn) * KB + wk4 * 4; \
        _Pragma("unroll") \
        for (int q = 0; q < 5; q++) wr[q] = *(const float4*)(wp + (size_t)q * 32 * NR_); }

#define XCP(nn, ss) { \
        const int xrow = t >> 2, xk8 = (t & 3) * 8; \
        const size_t so = (size_t)xrow * NR_ + r0 + (nn) * KB + xk8; \
        const uint32_t d = (uint32_t)((xrow * 40 + xk8) * 2) + (ss) * 5120; \
        cp16(sbase + XSH_OFF + d, Xh + so); \
        cp16(sbase + XSL_OFF + d, Xl + so); \
        cp_commit(); }

    XCP(0, 0);
    XCP(1, 1);
    LDGW(0);

    for (int n = 0; n < NCH; n++) {
        const int s2 = n & 1, s3 = n % 3;
        __syncthreads();                 // closes compute(n-1)
        // convert W chunk n -> ws[s2] (hi + residual lo)
#pragma unroll
        for (int q = 0; q < 5; q++) {
            union { __half h[4]; uint2 u; } ph, pl;
            hsplit(wr[q].x, ph.h[0], pl.h[0]);
            hsplit(wr[q].y, ph.h[1], pl.h[1]);
            hsplit(wr[q].z, ph.h[2], pl.h[2]);
            hsplit(wr[q].w, ph.h[3], pl.h[3]);
            const uint32_t d = (uint32_t)(((wrow + q * 32) * 40 + wk4 * 4) * 2)
                             + s2 * 12800;
            *(uint2*)(smem + WSH_OFF + d) = ph.u;
            *(uint2*)(smem + WSL_OFF + d) = pl.u;
        }
        if (n + 1 < NCH) LDGW(n + 1);
        if (n + 2 < NCH) { XCP(n + 2, (n + 2) % 3); }
        if (n + 2 < NCH)      cp_wait<2>();
        else if (n + 1 < NCH) cp_wait<1>();
        else                  cp_wait<0>();
        __syncthreads();                 // ws[s2] + xs[s3] ready

        const uint32_t wsh = sbase + WSH_OFF + s2 * 12800;
        const uint32_t wsl = sbase + WSL_OFF + s2 * 12800;
        const uint32_t xsh = sbase + XSH_OFF + s3 * 5120;
        const uint32_t xsl = sbase + XSL_OFF + s3 * 5120;
#pragma unroll
        for (int kb = 0; kb < 2; kb++) {
            // A fragments (x): 2 mt x (hi,lo) via ldmatrix.x4
            uint32_t ah[2][4], al[2][4];
#pragma unroll
            for (int mt = 0; mt < 2; mt++) {
                const uint32_t ao =
                    (uint32_t)(((wm * 32 + mt * 16 + a_ml) * 40 + kb * 16 + a_ko) * 2);
                ldsm4(ah[mt], xsh + ao);
                ldsm4(al[mt], xsl + ao);
            }
            // B fragments (W): nf pairs (0,1),(2,3) via x4; nf 4 via x2
            uint32_t bh[5][2], bl[5][2];
#pragma unroll
            for (int p = 0; p < 2; p++) {
                const uint32_t bo = (uint32_t)(
                    ((wn * 40 + (2 * p + b_p) * 8 + b_bn) * 40 + kb * 16 + b_ko) * 2);
                ldsm4(&bh[2 * p][0], wsh + bo);
                ldsm4(&bl[2 * p][0], wsl + bo);
            }
            {
                const uint32_t bo = (uint32_t)(
                    ((wn * 40 + 32 + b_bn) * 40 + kb * 16 + tC * 8) * 2);
                ldsm2(&bh[4][0], wsh + bo);
                ldsm2(&bl[4][0], wsl + bo);
            }
            // term-major: same-acc reuse distance = 10 MMAs
#pragma unroll
            for (int mt = 0; mt < 2; mt++)
#pragma unroll
                for (int nf = 0; nf < 5; nf++) mma16816(acc[mt][nf], ah[mt], bh[nf]);
#pragma unroll
            for (int mt = 0; mt < 2; mt++)
#pragma unroll
                for (int nf = 0; nf < 5; nf++) mma16816(acc[mt][nf], ah[mt], bl[nf]);
#pragma unroll
            for (int mt = 0; mt < 2; mt++)
#pragma unroll
                for (int nf = 0; nf < 5; nf++) mma16816(acc[mt][nf], al[mt], bh[nf]);
        }
    }

    // epilogue: g_part[split][b][i][co]
    float* base = g_part + (size_t)split * (B_ * IC_ * CO_) + (size_t)i * CO_;
#pragma unroll
    for (int mt = 0; mt < 2; mt++) {
        const int b = wm * 32 + mt * 16 + (lane >> 2);
#pragma unroll
        for (int nf = 0; nf < 5; nf++) {
            const int co = wn * 40 + nf * 8 + (lane & 3) * 2;
            float* d0 = base + (size_t)b * (IC_ * CO_) + co;
            *(float2*)d0 = make_float2(acc[mt][nf][0], acc[mt][nf][1]);
            *(float2*)(d0 + 8 * IC_ * CO_) =
                make_float2(acc[mt][nf][2], acc[mt][nf][3]);   // b+8
        }
    }
}

// ---------------------------------------------------------------------------
// 3) Fused split-K reduce + routing (3 iters) + v output + fc partials.
//    One CTA per capsule c, 1024 threads (t = b*16 + o).
// ---------------------------------------------------------------------------
#define ISTR 1032
__global__ __launch_bounds__(1024) void k_route_all(const float* __restrict__ fcw,
                                                    float* __restrict__ out) {
    extern __shared__ float sm[];
    float* u_s  = sm;                       // [16][ISTR]
    float* v_s  = sm + 16 * ISTR;           // [1024]
    float* csh  = v_s + 1024;               // [16]
    float* bijs = csh + 16;                 // [16]
    float* ared = bijs + 16;                // [32]
    const int c = blockIdx.x, t = threadIdx.x;

    {   // split-K reduce from L2-resident g_part
        const int o4 = t & 3, i = (t >> 2) & 15, b0 = t >> 6;
#pragma unroll
        for (int j = 0; j < 4; j++) {
            const int b = b0 + 16 * j;
            const size_t off = ((size_t)b * IC_ + i) * CO_ + c * OC_ + o4 * 4;
            float4 s = make_float4(0.f, 0.f, 0.f, 0.f);
#pragma unroll
            for (int sp = 0; sp < SPLITK; sp++) {
                float4 p = *(const float4*)(g_part + (size_t)sp * (B_ * IC_ * CO_) + off);
                s.x += p.x; s.y += p.y; s.z += p.z; s.w += p.w;
            }
            *(float4*)(u_s + i * ISTR + b * 16 + o4 * 4) = s;
        }
    }
    if (t < 16) bijs[t] = 0.f;
    __syncthreads();

    for (int it = 0; it < 3; it++) {
        if (t < 32) {   // softmax over i, width-16 shuffles
            float bv = (t < 16) ? bijs[t] : -1e30f;
            float m = bv;
#pragma unroll
            for (int off = 8; off; off >>= 1)
                m = fmaxf(m, __shfl_xor_sync(0xffffffffu, m, off, 16));
            float e = expf(bv - m), sum = e;
#pragma unroll
            for (int off = 8; off; off >>= 1)
                sum += __shfl_xor_sync(0xffffffffu, sum, off, 16);
            if (t < 16) csh[t] = e / sum;
        }
        __syncthreads();
        {
            float s = 0.f;
#pragma unroll
            for (int i = 0; i < IC_; i++) s += csh[i] * u_s[i * ISTR + t];
            v_s[t] = s * fabsf(s) / (1.f + s * s);
        }
        __syncthreads();
        if (it < 2) {   // agreement: 32 warps, (i, half) each
            const int w = t >> 5, l = t & 31;
            const int i = w & 15, j0 = (w >> 4) * 512;
            float a = 0.f;
            for (int j = j0 + l; j < j0 + 512; j += 32)
                a += u_s[i * ISTR + j] * v_s[j];
#pragma unroll
            for (int off = 16; off; off >>= 1)
                a += __shfl_down_sync(0xffffffffu, a, off);
            if (l == 0) ared[(w >> 4) * 16 + i] = a;
            __syncthreads();
            if (t < 16) bijs[t] += (ared[t] + ared[16 + t]) * (1.0f / B_);
            __syncthreads();
        }
    }
    {
        const int b = t >> 4, o = t & 15;
        const float v = v_s[t];
        out[B_ + b * CO_ + c * OC_ + o] = v;
        float p = v * fcw[c * OC_ + o];
#pragma unroll
        for (int off = 8; off; off >>= 1)
            p += __shfl_down_sync(0xffffffffu, p, off, 16);
        if (o == 0) g_fcp[c * B_ + b] = p;
    }
}

// ---------------------------------------------------------------------------
// 4) pred_b = sigmoid(sum_c fcp[c][b] + fc_b).  One CTA, 64 threads.
// ---------------------------------------------------------------------------
__global__ void k_final(const float* __restrict__ fcb, float* __restrict__ out) {
    const int b = threadIdx.x;
    float s = fcb[0];
#pragma unroll
    for (int c = 0; c < NC_; c++) s += g_fcp[c * B_ + b];
    out[b] = 1.f / (1.f + expf(-s));
}

// ---------------------------------------------------------------------------
extern "C" void kernel_launch(void* const* d_in, const int* in_sizes, int n_in,
                              void* d_out, int out_size) {
    const float* x   = (const float*)d_in[0];
    const float* W   = (const float*)d_in[1];
    const float* fcw = (const float*)d_in[2];
    const float* fcb = (const float*)d_in[3];
    float* out = (float*)d_out;

    const int route_smem = (16 * ISTR + 1024 + 16 + 16 + 32) * 4;
    cudaFuncSetAttribute(k_gemm, cudaFuncAttributeMaxDynamicSharedMemorySize, SMEM_G);
    cudaFuncSetAttribute(k_route_all, cudaFuncAttributeMaxDynamicSharedMemorySize,
                         route_smem);

    k_transpose<<<dim3(NR_ / 256, B_), 256>>>(x);
    k_gemm<<<dim3(SPLITK, IC_), 256, SMEM_G>>>(W);
    k_route_all<<<NC_, 1024, route_smem>>>(fcw, out);
    k_final<<<1, B_>>>(fcb, out);
}